// round 12
// baseline (speedup 1.0000x reference)
#include <cuda_runtime.h>
#include <cuda_bf16.h>
#include <cstdint>

#define DIMV   768
#define QKV3   2304
#define BATCH  8
#define SEQT   1024
#define NHEAD  12
#define HDIM   64
#define MROWS  (BATCH * SEQT)   // 8192
#define KP2    (DIMV / 2)       // 384 pair-words per row

// fp32 scratch
__device__ float g_qkv[(size_t)MROWS * QKV3];   // ~75.5 MB
__device__ float g_y[(size_t)MROWS * DIMV];     // ~25 MB
// packed bf16 hi/lo pair-words: word kp = {bf16(v[2kp]) in low16, bf16(v[2kp+1]) in high16}
__device__ uint32_t g_xh[(size_t)MROWS * KP2];      // x split        [M][384]
__device__ uint32_t g_xl[(size_t)MROWS * KP2];
__device__ uint32_t g_yh[(size_t)MROWS * KP2];      // attn out split [M][384]
__device__ uint32_t g_yl[(size_t)MROWS * KP2];
__device__ uint32_t g_wqh[(size_t)KP2 * QKV3];      // W_qkv packed   [384][2304]
__device__ uint32_t g_wql[(size_t)KP2 * QKV3];
__device__ uint32_t g_wph[(size_t)KP2 * DIMV];      // W_proj packed  [384][768]
__device__ uint32_t g_wpl[(size_t)KP2 * DIMV];

// ---------------------------------------------------------------------------
// Helpers
// ---------------------------------------------------------------------------
__device__ __forceinline__ uint32_t f2tf(float f) {
    uint32_t u;
    asm("cvt.rna.tf32.f32 %0, %1;" : "=r"(u) : "f"(f));
    return u;
}

__device__ __forceinline__ void mma_tf32(float* d,
                                         uint32_t a0, uint32_t a1, uint32_t a2, uint32_t a3,
                                         uint32_t b0, uint32_t b1)
{
    asm volatile(
        "mma.sync.aligned.m16n8k8.row.col.f32.tf32.tf32.f32 "
        "{%0,%1,%2,%3}, {%4,%5,%6,%7}, {%8,%9}, {%0,%1,%2,%3};\n"
        : "+f"(d[0]), "+f"(d[1]), "+f"(d[2]), "+f"(d[3])
        : "r"(a0), "r"(a1), "r"(a2), "r"(a3), "r"(b0), "r"(b1));
}

__device__ __forceinline__ void mma_bf16(float* d,
                                         uint32_t a0, uint32_t a1, uint32_t a2, uint32_t a3,
                                         uint32_t b0, uint32_t b1)
{
    asm volatile(
        "mma.sync.aligned.m16n8k16.row.col.f32.bf16.bf16.f32 "
        "{%0,%1,%2,%3}, {%4,%5,%6,%7}, {%8,%9}, {%0,%1,%2,%3};\n"
        : "+f"(d[0]), "+f"(d[1]), "+f"(d[2]), "+f"(d[3])
        : "r"(a0), "r"(a1), "r"(a2), "r"(a3), "r"(b0), "r"(b1));
}

// Split two floats (a = lower k index -> low half) into packed bf16 hi/lo words.
__device__ __forceinline__ void split2(float a, float b, uint32_t& h, uint32_t& l)
{
    __nv_bfloat16 ah = __float2bfloat16(a);
    __nv_bfloat16 bh = __float2bfloat16(b);
    h = ((uint32_t)__bfloat16_as_ushort(bh) << 16) | (uint32_t)__bfloat16_as_ushort(ah);
    __nv_bfloat16 al = __float2bfloat16(a - __bfloat162float(ah));
    __nv_bfloat16 bl = __float2bfloat16(b - __bfloat162float(bh));
    l = ((uint32_t)__bfloat16_as_ushort(bl) << 16) | (uint32_t)__bfloat16_as_ushort(al);
}

// ---------------------------------------------------------------------------
// Prepass 1: activation split  f32[M][768] -> packed hi/lo [M][384]
// ---------------------------------------------------------------------------
__global__ void split_f32_kernel(const float4* __restrict__ in,
                                 uint2* __restrict__ oh, uint2* __restrict__ ol,
                                 int n4)
{
    int i = blockIdx.x * blockDim.x + threadIdx.x;
    if (i >= n4) return;
    float4 v = in[i];
    uint32_t h0, l0, h1, l1;
    split2(v.x, v.y, h0, l0);
    split2(v.z, v.w, h1, l1);
    oh[i] = make_uint2(h0, h1);
    ol[i] = make_uint2(l0, l1);
}

// ---------------------------------------------------------------------------
// Prepass 2: weight pack  W f32[768][Nw] -> packed hi/lo [384][Nw]
// word(kp, n) = {W[2kp][n] (low16), W[2kp+1][n] (high16)}
// ---------------------------------------------------------------------------
__global__ void pack_w_kernel(const float* __restrict__ W,
                              uint32_t* __restrict__ oh, uint32_t* __restrict__ ol,
                              int Nw)
{
    int n  = blockIdx.x * 256 + threadIdx.x;
    int kp = blockIdx.y;
    float a = W[(size_t)(2 * kp) * Nw + n];
    float b = W[(size_t)(2 * kp + 1) * Nw + n];
    uint32_t h, l;
    split2(a, b, h, l);
    oh[(size_t)kp * Nw + n] = h;
    ol[(size_t)kp * Nw + n] = l;
}

// ---------------------------------------------------------------------------
// bf16x3 tensor-core GEMM on PRE-SPLIT operands, double-buffered smem.
// C[M,N] = A[M,768] @ B[768,N] + bias[N]
// CTA 128x128, BK=16 (8 pair-words), 8 warps (4M x 2N), warp tile 32x64.
// acc += Ah*Bh + Al*Bh + Ah*Bl.  Inner loop: LDG.128 -> STS.128 -> LDS -> HMMA.
// ---------------------------------------------------------------------------
#define AP   12
#define BP   136

__global__ __launch_bounds__(256, 2)
void bf16x3_gemm_bias_kernel(const uint32_t* __restrict__ Ahg,   // [M][384]
                             const uint32_t* __restrict__ Alg,
                             const uint32_t* __restrict__ Bhg,   // [384][N]
                             const uint32_t* __restrict__ Blg,
                             const float* __restrict__ bias,
                             float* __restrict__ C,
                             int N)
{
    __shared__ uint32_t Ah[2][128 * AP];
    __shared__ uint32_t Al[2][128 * AP];
    __shared__ uint32_t Bh[2][8 * BP];
    __shared__ uint32_t Bl[2][8 * BP];

    int tid  = threadIdx.x;
    int w    = tid >> 5;
    int lane = tid & 31;
    int gi   = lane >> 2;
    int tg   = lane & 3;
    int wm   = (w & 3) * 32;
    int wn   = (w >> 2) * 64;
    int m0   = blockIdx.y * 128;
    int n0   = blockIdx.x * 128;

    // A staging: row = tid>>1 (0..127), word group (tid&1)*4
    int arow = tid >> 1;
    int aw4  = (tid & 1) * 4;
    // B staging: kp-row = tid>>5 (0..7), cols (tid&31)*4
    int bkp  = tid >> 5;
    int bn4  = (tid & 31) * 4;

    const uint4* ApH = (const uint4*)(Ahg + (size_t)(m0 + arow) * KP2 + aw4);
    const uint4* ApL = (const uint4*)(Alg + (size_t)(m0 + arow) * KP2 + aw4);
    const uint4* BpH = (const uint4*)(Bhg + (size_t)bkp * N + n0 + bn4);
    const uint4* BpL = (const uint4*)(Blg + (size_t)bkp * N + n0 + bn4);

    float acc[2][8][4];
    #pragma unroll
    for (int mi = 0; mi < 2; mi++)
        #pragma unroll
        for (int nb = 0; nb < 8; nb++)
            #pragma unroll
            for (int e = 0; e < 4; e++) acc[mi][nb][e] = 0.f;

    // Prologue: stage chunk 0 into buffer 0
    {
        *(uint4*)&Ah[0][arow * AP + aw4] = ApH[0];
        *(uint4*)&Al[0][arow * AP + aw4] = ApL[0];
        *(uint4*)&Bh[0][bkp * BP + bn4]  = BpH[0];
        *(uint4*)&Bl[0][bkp * BP + bn4]  = BpL[0];
    }
    __syncthreads();

    const int NCH = KP2 / 8;       // 48 chunks of 8 pair-words (k16)
    int cur = 0;
    for (int ch = 0; ch < NCH; ch++) {
        bool has_next = (ch + 1 < NCH);
        uint4 pa0, pa1, pb0, pb1;
        if (has_next) {
            // next-chunk LDGs in flight during mma
            pa0 = ApH[(ch + 1) * 2];               // +8 words = 2 uint4
            pa1 = ApL[(ch + 1) * 2];
            pb0 = *(const uint4*)((const uint32_t*)BpH + (size_t)(ch + 1) * 8 * N);
            pb1 = *(const uint4*)((const uint32_t*)BpL + (size_t)(ch + 1) * 8 * N);
        }

        // MMA on buffer cur
        uint32_t ah[2][4], al[2][4];
        #pragma unroll
        for (int mi = 0; mi < 2; mi++) {
            int r = wm + mi * 16 + gi;
            ah[mi][0] = Ah[cur][r * AP + tg];
            ah[mi][1] = Ah[cur][(r + 8) * AP + tg];
            ah[mi][2] = Ah[cur][r * AP + tg + 4];
            ah[mi][3] = Ah[cur][(r + 8) * AP + tg + 4];
            al[mi][0] = Al[cur][r * AP + tg];
            al[mi][1] = Al[cur][(r + 8) * AP + tg];
            al[mi][2] = Al[cur][r * AP + tg + 4];
            al[mi][3] = Al[cur][(r + 8) * AP + tg + 4];
        }
        #pragma unroll
        for (int nb = 0; nb < 8; nb++) {
            int c = wn + nb * 8 + gi;
            uint32_t bh0 = Bh[cur][tg * BP + c];
            uint32_t bh1 = Bh[cur][(tg + 4) * BP + c];
            uint32_t bl0 = Bl[cur][tg * BP + c];
            uint32_t bl1 = Bl[cur][(tg + 4) * BP + c];
            #pragma unroll
            for (int mi = 0; mi < 2; mi++) {
                mma_bf16(acc[mi][nb], ah[mi][0], ah[mi][1], ah[mi][2], ah[mi][3], bh0, bh1);
                mma_bf16(acc[mi][nb], al[mi][0], al[mi][1], al[mi][2], al[mi][3], bh0, bh1);
                mma_bf16(acc[mi][nb], ah[mi][0], ah[mi][1], ah[mi][2], ah[mi][3], bl0, bl1);
            }
        }

        if (has_next) {
            int nxt = cur ^ 1;
            *(uint4*)&Ah[nxt][arow * AP + aw4] = pa0;
            *(uint4*)&Al[nxt][arow * AP + aw4] = pa1;
            *(uint4*)&Bh[nxt][bkp * BP + bn4]  = pb0;
            *(uint4*)&Bl[nxt][bkp * BP + bn4]  = pb1;
        }
        __syncthreads();
        cur ^= 1;
    }

    // Epilogue: bias + store
    #pragma unroll
    for (int mi = 0; mi < 2; mi++) {
        int r = m0 + wm + mi * 16 + gi;
        #pragma unroll
        for (int nb = 0; nb < 8; nb++) {
            int c = n0 + wn + nb * 8 + 2 * tg;
            float2 bv = *(const float2*)&bias[c];
            *(float2*)&C[(size_t)r * N + c] =
                make_float2(acc[mi][nb][0] + bv.x, acc[mi][nb][1] + bv.y);
            *(float2*)&C[(size_t)(r + 8) * N + c] =
                make_float2(acc[mi][nb][2] + bv.x, acc[mi][nb][3] + bv.y);
        }
    }
}

// ---------------------------------------------------------------------------
// Flash attention (unchanged from R9):
//   QK tf32, softmax in regs, PV bf16 fragment-reuse 3-term, 2 CTAs/SM.
// ---------------------------------------------------------------------------
#define BQ     128
#define BKV    128
#define QKP    68
#define VP     72

#define QS_OFF  0
#define KS_OFF  (QS_OFF + BQ * QKP)
#define VH_OFF  (KS_OFF + BKV * QKP)
#define VL_OFF  (VH_OFF + (BKV/2) * VP)
#define SMEM_WORDS (VL_OFF + (BKV/2) * VP)

__global__ __launch_bounds__(256, 2)
void flash_attn_tc_kernel(const float* __restrict__ qkv, float* __restrict__ y)
{
    extern __shared__ uint32_t sm[];
    uint32_t* Qs = sm + QS_OFF;
    uint32_t* Ks = sm + KS_OFF;
    uint32_t* Vh = sm + VH_OFF;
    uint32_t* Vl = sm + VL_OFF;

    int tid  = threadIdx.x;
    int w    = tid >> 5;
    int lane = tid & 31;
    int gi   = lane >> 2;
    int tg   = lane & 3;
    int q0   = blockIdx.x * BQ;
    int h    = blockIdx.y;
    int b    = blockIdx.z;
    const float SCALE = 0.125f;

    size_t base = (size_t)b * SEQT * QKV3;
    int qoff = h * HDIM;
    int koff = DIMV + h * HDIM;
    int voff = 2 * DIMV + h * HDIM;

    #pragma unroll
    for (int it = 0; it < 8; it++) {
        int idx = tid + it * 256;
        int r   = idx >> 4;
        int c4  = (idx & 15) * 4;
        float4 v = *(const float4*)&qkv[base + (size_t)(q0 + r) * QKV3 + qoff + c4];
        uint4 t;
        t.x = f2tf(v.x); t.y = f2tf(v.y); t.z = f2tf(v.z); t.w = f2tf(v.w);
        *(uint4*)&Qs[r * QKP + c4] = t;
    }

    int r0 = w * 16 + gi;
    int r1 = r0 + 8;

    float m0 = -1e30f, m1 = -1e30f;
    float l0 = 0.f, l1 = 0.f;
    float o[8][4];
    #pragma unroll
    for (int j = 0; j < 8; j++)
        #pragma unroll
        for (int e = 0; e < 4; e++) o[j][e] = 0.f;

    for (int kv0 = 0; kv0 < SEQT; kv0 += BKV) {
        __syncthreads();

        #pragma unroll
        for (int it = 0; it < 8; it++) {
            int idx = tid + it * 256;
            int r   = idx >> 4;
            int c4  = (idx & 15) * 4;
            size_t row = base + (size_t)(kv0 + r) * QKV3;
            float4 kvv = *(const float4*)&qkv[row + koff + c4];
            uint4 tk;
            tk.x = f2tf(kvv.x); tk.y = f2tf(kvv.y); tk.z = f2tf(kvv.z); tk.w = f2tf(kvv.w);
            *(uint4*)&Ks[r * QKP + c4] = tk;
        }
        #pragma unroll
        for (int it = 0; it < 4; it++) {
            int t   = tid + it * 256;
            int kp  = t >> 4;
            int c4  = (t & 15) * 4;
            size_t rowa = base + (size_t)(kv0 + 2 * kp) * QKV3 + voff + c4;
            size_t rowb = rowa + QKV3;
            float4 va = *(const float4*)&qkv[rowa];
            float4 vb = *(const float4*)&qkv[rowb];
            uint4 hh, ll;
            split2(va.x, vb.x, hh.x, ll.x);
            split2(va.y, vb.y, hh.y, ll.y);
            split2(va.z, vb.z, hh.z, ll.z);
            split2(va.w, vb.w, hh.w, ll.w);
            *(uint4*)&Vh[kp * VP + c4] = hh;
            *(uint4*)&Vl[kp * VP + c4] = ll;
        }
        __syncthreads();

        float s[16][4];
        #pragma unroll
        for (int j = 0; j < 16; j++)
            #pragma unroll
            for (int e = 0; e < 4; e++) s[j][e] = 0.f;

        #pragma unroll
        for (int kk = 0; kk < 8; kk++) {
            int d0 = kk * 8;
            uint32_t a0 = Qs[r0 * QKP + d0 + tg];
            uint32_t a1 = Qs[r1 * QKP + d0 + tg];
            uint32_t a2 = Qs[r0 * QKP + d0 + tg + 4];
            uint32_t a3 = Qs[r1 * QKP + d0 + tg + 4];
            #pragma unroll
            for (int j = 0; j < 16; j++) {
                uint32_t b0 = Ks[(j * 8 + gi) * QKP + d0 + tg];
                uint32_t b1 = Ks[(j * 8 + gi) * QKP + d0 + tg + 4];
                mma_tf32(s[j], a0, a1, a2, a3, b0, b1);
            }
        }

        float mx0 = -1e30f, mx1 = -1e30f;
        #pragma unroll
        for (int j = 0; j < 16; j++) {
            mx0 = fmaxf(mx0, fmaxf(s[j][0], s[j][1]));
            mx1 = fmaxf(mx1, fmaxf(s[j][2], s[j][3]));
        }
        #pragma unroll
        for (int msk = 1; msk < 4; msk <<= 1) {
            mx0 = fmaxf(mx0, __shfl_xor_sync(0xffffffffu, mx0, msk));
            mx1 = fmaxf(mx1, __shfl_xor_sync(0xffffffffu, mx1, msk));
        }
        float mn0 = fmaxf(m0, mx0 * SCALE);
        float mn1 = fmaxf(m1, mx1 * SCALE);
        float c0 = __expf(m0 - mn0);
        float c1 = __expf(m1 - mn1);

        float sum0 = 0.f, sum1 = 0.f;
        #pragma unroll
        for (int j = 0; j < 16; j++) {
            s[j][0] = __expf(s[j][0] * SCALE - mn0);
            s[j][1] = __expf(s[j][1] * SCALE - mn0);
            s[j][2] = __expf(s[j][2] * SCALE - mn1);
            s[j][3] = __expf(s[j][3] * SCALE - mn1);
            sum0 += s[j][0] + s[j][1];
            sum1 += s[j][2] + s[j][3];
        }
        #pragma unroll
        for (int msk = 1; msk < 4; msk <<= 1) {
            sum0 += __shfl_xor_sync(0xffffffffu, sum0, msk);
            sum1 += __shfl_xor_sync(0xffffffffu, sum1, msk);
        }
        l0 = l0 * c0 + sum0;
        l1 = l1 * c1 + sum1;
        m0 = mn0;
        m1 = mn1;
        #pragma unroll
        for (int j = 0; j < 8; j++) {
            o[j][0] *= c0; o[j][1] *= c0;
            o[j][2] *= c1; o[j][3] *= c1;
        }

        #pragma unroll
        for (int kk = 0; kk < 8; kk++) {
            uint32_t ph[4], pl[4];
            split2(s[2 * kk][0],     s[2 * kk][1],     ph[0], pl[0]);
            split2(s[2 * kk][2],     s[2 * kk][3],     ph[1], pl[1]);
            split2(s[2 * kk + 1][0], s[2 * kk + 1][1], ph[2], pl[2]);
            split2(s[2 * kk + 1][2], s[2 * kk + 1][3], ph[3], pl[3]);
            #pragma unroll
            for (int j = 0; j < 8; j++) {
                int c = j * 8 + gi;
                uint32_t bh0 = Vh[(8 * kk + tg) * VP + c];
                uint32_t bh1 = Vh[(8 * kk + tg + 4) * VP + c];
                uint32_t bl0 = Vl[(8 * kk + tg) * VP + c];
                uint32_t bl1 = Vl[(8 * kk + tg + 4) * VP + c];
                mma_bf16(o[j], ph[0], ph[1], ph[2], ph[3], bh0, bh1);
                mma_bf16(o[j], pl[0], pl[1], pl[2], pl[3], bh0, bh1);
                mma_bf16(o[j], ph[0], ph[1], ph[2], ph[3], bl0, bl1);
            }
        }
    }

    float inv0 = 1.f / l0;
    float inv1 = 1.f / l1;
    size_t row0 = (size_t)(b * SEQT + q0 + r0) * DIMV + h * HDIM;
    size_t row1 = (size_t)(b * SEQT + q0 + r1) * DIMV + h * HDIM;
    #pragma unroll
    for (int j = 0; j < 8; j++) {
        int col = j * 8 + 2 * tg;
        *(float2*)&y[row0 + col] = make_float2(o[j][0] * inv0, o[j][1] * inv0);
        *(float2*)&y[row1 + col] = make_float2(o[j][2] * inv1, o[j][3] * inv1);
    }
}

// ---------------------------------------------------------------------------
extern "C" void kernel_launch(void* const* d_in, const int* in_sizes, int n_in,
                              void* d_out, int out_size)
{
    const float* x      = (const float*)d_in[0];
    const float* W_qkv  = (const float*)d_in[1];
    const float* b_qkv  = (const float*)d_in[2];
    const float* W_proj = (const float*)d_in[3];
    const float* b_proj = (const float*)d_in[4];
    float* out = (float*)d_out;

    float *qkv, *yb;
    uint32_t *xh, *xl, *yh, *yl, *wqh, *wql, *wph, *wpl;
    cudaGetSymbolAddress((void**)&qkv, g_qkv);
    cudaGetSymbolAddress((void**)&yb,  g_y);
    cudaGetSymbolAddress((void**)&xh,  g_xh);
    cudaGetSymbolAddress((void**)&xl,  g_xl);
    cudaGetSymbolAddress((void**)&yh,  g_yh);
    cudaGetSymbolAddress((void**)&yl,  g_yl);
    cudaGetSymbolAddress((void**)&wqh, g_wqh);
    cudaGetSymbolAddress((void**)&wql, g_wql);
    cudaGetSymbolAddress((void**)&wph, g_wph);
    cudaGetSymbolAddress((void**)&wpl, g_wpl);

    int n4 = MROWS * DIMV / 4;

    // Prepasses: split x; pack both weights
    split_f32_kernel<<<(n4 + 255) / 256, 256>>>((const float4*)x,
                                                (uint2*)xh, (uint2*)xl, n4);
    pack_w_kernel<<<dim3(QKV3 / 256, KP2), 256>>>(W_qkv, wqh, wql, QKV3);
    pack_w_kernel<<<dim3(DIMV / 256, KP2), 256>>>(W_proj, wph, wpl, DIMV);

    // 1) QKV projection (bf16x3, pre-split operands)
    bf16x3_gemm_bias_kernel<<<dim3(QKV3 / 128, MROWS / 128), 256>>>(
        xh, xl, wqh, wql, b_qkv, qkv, QKV3);

    // 2) Flash attention
    {
        int smem_bytes = SMEM_WORDS * 4;
        cudaFuncSetAttribute(flash_attn_tc_kernel,
                             cudaFuncAttributeMaxDynamicSharedMemorySize, smem_bytes);
        dim3 grid(SEQT / BQ, NHEAD, BATCH);
        flash_attn_tc_kernel<<<grid, 256, smem_bytes>>>(qkv, yb);
    }

    // 3) Split attention output, then output projection
    split_f32_kernel<<<(n4 + 255) / 256, 256>>>((const float4*)yb,
                                                (uint2*)yh, (uint2*)yl, n4);
    bf16x3_gemm_bias_kernel<<<dim3(DIMV / 128, MROWS / 128), 256>>>(
        yh, yl, wph, wpl, b_proj, out, DIMV);
}

// round 13
// speedup vs baseline: 1.0076x; 1.0076x over previous
#include <cuda_runtime.h>
#include <cuda_bf16.h>
#include <cstdint>

#define DIMV   768
#define QKV3   2304
#define BATCH  8
#define SEQT   1024
#define NHEAD  12
#define HDIM   64
#define MROWS  (BATCH * SEQT)   // 8192
#define KP2    (DIMV / 2)       // 384 pair-words per row

// fp32 scratch
__device__ float g_qkv[(size_t)MROWS * QKV3];   // ~75.5 MB
// packed bf16 hi/lo pair-words: word kp = {bf16(v[2kp]) low16, bf16(v[2kp+1]) high16}
__device__ uint32_t g_xh[(size_t)MROWS * KP2];
__device__ uint32_t g_xl[(size_t)MROWS * KP2];
__device__ uint32_t g_yh[(size_t)MROWS * KP2];      // attn out (written packed by attention)
__device__ uint32_t g_yl[(size_t)MROWS * KP2];
__device__ uint32_t g_wqh[(size_t)KP2 * QKV3];
__device__ uint32_t g_wql[(size_t)KP2 * QKV3];
__device__ uint32_t g_wph[(size_t)KP2 * DIMV];
__device__ uint32_t g_wpl[(size_t)KP2 * DIMV];

// ---------------------------------------------------------------------------
// Helpers
// ---------------------------------------------------------------------------
__device__ __forceinline__ uint32_t f2tf(float f) {
    uint32_t u;
    asm("cvt.rna.tf32.f32 %0, %1;" : "=r"(u) : "f"(f));
    return u;
}

__device__ __forceinline__ uint32_t smem_to_u32(const void* p) {
    uint32_t a;
    asm("{ .reg .u64 t; cvta.to.shared.u64 t, %1; cvt.u32.u64 %0, t; }"
        : "=r"(a) : "l"(p));
    return a;
}

__device__ __forceinline__ void cp_async16(uint32_t saddr, const void* gptr) {
    asm volatile("cp.async.cg.shared.global [%0], [%1], 16;"
                 :: "r"(saddr), "l"(gptr));
}
#define CP_COMMIT() asm volatile("cp.async.commit_group;" ::: "memory")
#define CP_WAIT1()  asm volatile("cp.async.wait_group 1;" ::: "memory")

__device__ __forceinline__ void mma_tf32(float* d,
                                         uint32_t a0, uint32_t a1, uint32_t a2, uint32_t a3,
                                         uint32_t b0, uint32_t b1)
{
    asm volatile(
        "mma.sync.aligned.m16n8k8.row.col.f32.tf32.tf32.f32 "
        "{%0,%1,%2,%3}, {%4,%5,%6,%7}, {%8,%9}, {%0,%1,%2,%3};\n"
        : "+f"(d[0]), "+f"(d[1]), "+f"(d[2]), "+f"(d[3])
        : "r"(a0), "r"(a1), "r"(a2), "r"(a3), "r"(b0), "r"(b1));
}

__device__ __forceinline__ void mma_bf16(float* d,
                                         uint32_t a0, uint32_t a1, uint32_t a2, uint32_t a3,
                                         uint32_t b0, uint32_t b1)
{
    asm volatile(
        "mma.sync.aligned.m16n8k16.row.col.f32.bf16.bf16.f32 "
        "{%0,%1,%2,%3}, {%4,%5,%6,%7}, {%8,%9}, {%0,%1,%2,%3};\n"
        : "+f"(d[0]), "+f"(d[1]), "+f"(d[2]), "+f"(d[3])
        : "r"(a0), "r"(a1), "r"(a2), "r"(a3), "r"(b0), "r"(b1));
}

__device__ __forceinline__ void split2(float a, float b, uint32_t& h, uint32_t& l)
{
    __nv_bfloat16 ah = __float2bfloat16(a);
    __nv_bfloat16 bh = __float2bfloat16(b);
    h = ((uint32_t)__bfloat16_as_ushort(bh) << 16) | (uint32_t)__bfloat16_as_ushort(ah);
    __nv_bfloat16 al = __float2bfloat16(a - __bfloat162float(ah));
    __nv_bfloat16 bl = __float2bfloat16(b - __bfloat162float(bh));
    l = ((uint32_t)__bfloat16_as_ushort(bl) << 16) | (uint32_t)__bfloat16_as_ushort(al);
}

// ---------------------------------------------------------------------------
// Prepass 1: activation split  f32[M][768] -> packed hi/lo [M][384]
// ---------------------------------------------------------------------------
__global__ void split_f32_kernel(const float4* __restrict__ in,
                                 uint2* __restrict__ oh, uint2* __restrict__ ol,
                                 int n4)
{
    int i = blockIdx.x * blockDim.x + threadIdx.x;
    if (i >= n4) return;
    float4 v = in[i];
    uint32_t h0, l0, h1, l1;
    split2(v.x, v.y, h0, l0);
    split2(v.z, v.w, h1, l1);
    oh[i] = make_uint2(h0, h1);
    ol[i] = make_uint2(l0, l1);
}

// ---------------------------------------------------------------------------
// Prepass 2: weight pack  W f32[768][Nw] -> packed hi/lo [384][Nw]
// ---------------------------------------------------------------------------
__global__ void pack_w_kernel(const float* __restrict__ W,
                              uint32_t* __restrict__ oh, uint32_t* __restrict__ ol,
                              int Nw)
{
    int n  = blockIdx.x * 256 + threadIdx.x;
    int kp = blockIdx.y;
    float a = W[(size_t)(2 * kp) * Nw + n];
    float b = W[(size_t)(2 * kp + 1) * Nw + n];
    uint32_t h, l;
    split2(a, b, h, l);
    oh[(size_t)kp * Nw + n] = h;
    ol[(size_t)kp * Nw + n] = l;
}

// ---------------------------------------------------------------------------
// bf16x3 GEMM, cp.async 3-stage pipeline.
// C[M,N] = A[M,768] @ B[768,N] + bias[N]
// CTA 128x128, BK=16 (8 pair-words), 8 warps (4M x 2N), warp tile 32x64.
// Stage layout (words): Ah[128*12] | Al[128*12] | Bh[8*136] | Bl[8*136]
// ---------------------------------------------------------------------------
#define AP     12
#define BP     136
#define AH_O   0
#define AL_O   1536
#define BH_O   3072
#define BL_O   4160
#define STG_W  5248
#define NSTAGE 3
#define GEMM_SMEM (NSTAGE * STG_W * 4)    // 62976 B

__global__ __launch_bounds__(256, 2)
void bf16x3_gemm_bias_kernel(const uint32_t* __restrict__ Ahg,   // [M][384]
                             const uint32_t* __restrict__ Alg,
                             const uint32_t* __restrict__ Bhg,   // [384][N]
                             const uint32_t* __restrict__ Blg,
                             const float* __restrict__ bias,
                             float* __restrict__ C,
                             int N)
{
    extern __shared__ __align__(16) uint32_t smg[];
    uint32_t sbase = smem_to_u32(smg);

    int tid  = threadIdx.x;
    int w    = tid >> 5;
    int lane = tid & 31;
    int gi   = lane >> 2;
    int tg   = lane & 3;
    int wm   = (w & 3) * 32;
    int wn   = (w >> 2) * 64;
    int m0   = blockIdx.y * 128;
    int n0   = blockIdx.x * 128;

    // staging mapping
    int arow = tid >> 1;             // 0..127
    int aw4  = (tid & 1) * 4;        // 0 or 4
    int bkp  = tid >> 5;             // 0..7
    int bn4  = (tid & 31) * 4;

    uint32_t a_soff = (uint32_t)(arow * AP + aw4) * 4;
    uint32_t b_soff = (uint32_t)(bkp * BP + bn4) * 4;
    const uint32_t* gAh = Ahg + (size_t)(m0 + arow) * KP2 + aw4;
    const uint32_t* gAl = Alg + (size_t)(m0 + arow) * KP2 + aw4;
    const uint32_t* gBh = Bhg + (size_t)bkp * N + n0 + bn4;
    const uint32_t* gBl = Blg + (size_t)bkp * N + n0 + bn4;

    const int NCH = KP2 / 8;         // 48 chunks of 8 pair-words (k16)

    float acc[2][8][4];
    #pragma unroll
    for (int mi = 0; mi < 2; mi++)
        #pragma unroll
        for (int nb = 0; nb < 8; nb++)
            #pragma unroll
            for (int e = 0; e < 4; e++) acc[mi][nb][e] = 0.f;

    // Prologue: issue stages 0 and 1
    #pragma unroll
    for (int p = 0; p < 2; p++) {
        uint32_t sb = sbase + p * STG_W * 4;
        cp_async16(sb + AH_O * 4 + a_soff, gAh + p * 8);
        cp_async16(sb + AL_O * 4 + a_soff, gAl + p * 8);
        cp_async16(sb + BH_O * 4 + b_soff, gBh + (size_t)p * 8 * N);
        cp_async16(sb + BL_O * 4 + b_soff, gBl + (size_t)p * 8 * N);
        CP_COMMIT();
    }

    int st = 0;
    for (int ch = 0; ch < NCH; ch++) {
        CP_WAIT1();            // stage ch complete (<=1 group pending)
        __syncthreads();

        // Issue stage ch+2 (overwrites buffer of ch-1; all warps past its reads)
        if (ch + 2 < NCH) {
            int ns = st + 2;
            if (ns >= NSTAGE) ns -= NSTAGE;
            uint32_t sb = sbase + ns * STG_W * 4;
            cp_async16(sb + AH_O * 4 + a_soff, gAh + (ch + 2) * 8);
            cp_async16(sb + AL_O * 4 + a_soff, gAl + (ch + 2) * 8);
            cp_async16(sb + BH_O * 4 + b_soff, gBh + (size_t)(ch + 2) * 8 * N);
            cp_async16(sb + BL_O * 4 + b_soff, gBl + (size_t)(ch + 2) * 8 * N);
        }
        CP_COMMIT();           // always commit (empty groups keep the count uniform)

        const uint32_t* S = smg + st * STG_W;

        uint32_t ah[2][4], al[2][4];
        #pragma unroll
        for (int mi = 0; mi < 2; mi++) {
            int r = wm + mi * 16 + gi;
            ah[mi][0] = S[AH_O + r * AP + tg];
            ah[mi][1] = S[AH_O + (r + 8) * AP + tg];
            ah[mi][2] = S[AH_O + r * AP + tg + 4];
            ah[mi][3] = S[AH_O + (r + 8) * AP + tg + 4];
            al[mi][0] = S[AL_O + r * AP + tg];
            al[mi][1] = S[AL_O + (r + 8) * AP + tg];
            al[mi][2] = S[AL_O + r * AP + tg + 4];
            al[mi][3] = S[AL_O + (r + 8) * AP + tg + 4];
        }
        #pragma unroll
        for (int nb = 0; nb < 8; nb++) {
            int c = wn + nb * 8 + gi;
            uint32_t bh0 = S[BH_O + tg * BP + c];
            uint32_t bh1 = S[BH_O + (tg + 4) * BP + c];
            uint32_t bl0 = S[BL_O + tg * BP + c];
            uint32_t bl1 = S[BL_O + (tg + 4) * BP + c];
            #pragma unroll
            for (int mi = 0; mi < 2; mi++) {
                mma_bf16(acc[mi][nb], ah[mi][0], ah[mi][1], ah[mi][2], ah[mi][3], bh0, bh1);
                mma_bf16(acc[mi][nb], al[mi][0], al[mi][1], al[mi][2], al[mi][3], bh0, bh1);
                mma_bf16(acc[mi][nb], ah[mi][0], ah[mi][1], ah[mi][2], ah[mi][3], bl0, bl1);
            }
        }

        if (++st == NSTAGE) st = 0;
    }

    // Epilogue: bias + store
    #pragma unroll
    for (int mi = 0; mi < 2; mi++) {
        int r = m0 + wm + mi * 16 + gi;
        #pragma unroll
        for (int nb = 0; nb < 8; nb++) {
            int c = n0 + wn + nb * 8 + 2 * tg;
            float2 bv = *(const float2*)&bias[c];
            *(float2*)&C[(size_t)r * N + c] =
                make_float2(acc[mi][nb][0] + bv.x, acc[mi][nb][1] + bv.y);
            *(float2*)&C[(size_t)(r + 8) * N + c] =
                make_float2(acc[mi][nb][2] + bv.x, acc[mi][nb][3] + bv.y);
        }
    }
}

// ---------------------------------------------------------------------------
// Flash attention: QK tf32, softmax in regs, PV bf16 fragment-reuse 3-term.
// Epilogue writes PACKED bf16 hi/lo directly (fused y-split).
// ---------------------------------------------------------------------------
#define BQ     128
#define BKV    128
#define QKP    68
#define VP     72

#define QS_OFF  0
#define KS_OFF  (QS_OFF + BQ * QKP)
#define VH_OFF  (KS_OFF + BKV * QKP)
#define VL_OFF  (VH_OFF + (BKV/2) * VP)
#define SMEM_WORDS (VL_OFF + (BKV/2) * VP)

__global__ __launch_bounds__(256, 2)
void flash_attn_tc_kernel(const float* __restrict__ qkv,
                          uint32_t* __restrict__ yh, uint32_t* __restrict__ yl)
{
    extern __shared__ uint32_t sm[];
    uint32_t* Qs = sm + QS_OFF;
    uint32_t* Ks = sm + KS_OFF;
    uint32_t* Vh = sm + VH_OFF;
    uint32_t* Vl = sm + VL_OFF;

    int tid  = threadIdx.x;
    int w    = tid >> 5;
    int lane = tid & 31;
    int gi   = lane >> 2;
    int tg   = lane & 3;
    int q0   = blockIdx.x * BQ;
    int h    = blockIdx.y;
    int b    = blockIdx.z;
    const float SCALE = 0.125f;

    size_t base = (size_t)b * SEQT * QKV3;
    int qoff = h * HDIM;
    int koff = DIMV + h * HDIM;
    int voff = 2 * DIMV + h * HDIM;

    #pragma unroll
    for (int it = 0; it < 8; it++) {
        int idx = tid + it * 256;
        int r   = idx >> 4;
        int c4  = (idx & 15) * 4;
        float4 v = *(const float4*)&qkv[base + (size_t)(q0 + r) * QKV3 + qoff + c4];
        uint4 t;
        t.x = f2tf(v.x); t.y = f2tf(v.y); t.z = f2tf(v.z); t.w = f2tf(v.w);
        *(uint4*)&Qs[r * QKP + c4] = t;
    }

    int r0 = w * 16 + gi;
    int r1 = r0 + 8;

    float m0 = -1e30f, m1 = -1e30f;
    float l0 = 0.f, l1 = 0.f;
    float o[8][4];
    #pragma unroll
    for (int j = 0; j < 8; j++)
        #pragma unroll
        for (int e = 0; e < 4; e++) o[j][e] = 0.f;

    for (int kv0 = 0; kv0 < SEQT; kv0 += BKV) {
        __syncthreads();

        #pragma unroll
        for (int it = 0; it < 8; it++) {
            int idx = tid + it * 256;
            int r   = idx >> 4;
            int c4  = (idx & 15) * 4;
            size_t row = base + (size_t)(kv0 + r) * QKV3;
            float4 kvv = *(const float4*)&qkv[row + koff + c4];
            uint4 tk;
            tk.x = f2tf(kvv.x); tk.y = f2tf(kvv.y); tk.z = f2tf(kvv.z); tk.w = f2tf(kvv.w);
            *(uint4*)&Ks[r * QKP + c4] = tk;
        }
        #pragma unroll
        for (int it = 0; it < 4; it++) {
            int t   = tid + it * 256;
            int kp  = t >> 4;
            int c4  = (t & 15) * 4;
            size_t rowa = base + (size_t)(kv0 + 2 * kp) * QKV3 + voff + c4;
            size_t rowb = rowa + QKV3;
            float4 va = *(const float4*)&qkv[rowa];
            float4 vb = *(const float4*)&qkv[rowb];
            uint4 hh, ll;
            split2(va.x, vb.x, hh.x, ll.x);
            split2(va.y, vb.y, hh.y, ll.y);
            split2(va.z, vb.z, hh.z, ll.z);
            split2(va.w, vb.w, hh.w, ll.w);
            *(uint4*)&Vh[kp * VP + c4] = hh;
            *(uint4*)&Vl[kp * VP + c4] = ll;
        }
        __syncthreads();

        float s[16][4];
        #pragma unroll
        for (int j = 0; j < 16; j++)
            #pragma unroll
            for (int e = 0; e < 4; e++) s[j][e] = 0.f;

        #pragma unroll
        for (int kk = 0; kk < 8; kk++) {
            int d0 = kk * 8;
            uint32_t a0 = Qs[r0 * QKP + d0 + tg];
            uint32_t a1 = Qs[r1 * QKP + d0 + tg];
            uint32_t a2 = Qs[r0 * QKP + d0 + tg + 4];
            uint32_t a3 = Qs[r1 * QKP + d0 + tg + 4];
            #pragma unroll
            for (int j = 0; j < 16; j++) {
                uint32_t b0 = Ks[(j * 8 + gi) * QKP + d0 + tg];
                uint32_t b1 = Ks[(j * 8 + gi) * QKP + d0 + tg + 4];
                mma_tf32(s[j], a0, a1, a2, a3, b0, b1);
            }
        }

        float mx0 = -1e30f, mx1 = -1e30f;
        #pragma unroll
        for (int j = 0; j < 16; j++) {
            mx0 = fmaxf(mx0, fmaxf(s[j][0], s[j][1]));
            mx1 = fmaxf(mx1, fmaxf(s[j][2], s[j][3]));
        }
        #pragma unroll
        for (int msk = 1; msk < 4; msk <<= 1) {
            mx0 = fmaxf(mx0, __shfl_xor_sync(0xffffffffu, mx0, msk));
            mx1 = fmaxf(mx1, __shfl_xor_sync(0xffffffffu, mx1, msk));
        }
        float mn0 = fmaxf(m0, mx0 * SCALE);
        float mn1 = fmaxf(m1, mx1 * SCALE);
        float c0 = __expf(m0 - mn0);
        float c1 = __expf(m1 - mn1);

        float sum0 = 0.f, sum1 = 0.f;
        #pragma unroll
        for (int j = 0; j < 16; j++) {
            s[j][0] = __expf(s[j][0] * SCALE - mn0);
            s[j][1] = __expf(s[j][1] * SCALE - mn0);
            s[j][2] = __expf(s[j][2] * SCALE - mn1);
            s[j][3] = __expf(s[j][3] * SCALE - mn1);
            sum0 += s[j][0] + s[j][1];
            sum1 += s[j][2] + s[j][3];
        }
        #pragma unroll
        for (int msk = 1; msk < 4; msk <<= 1) {
            sum0 += __shfl_xor_sync(0xffffffffu, sum0, msk);
            sum1 += __shfl_xor_sync(0xffffffffu, sum1, msk);
        }
        l0 = l0 * c0 + sum0;
        l1 = l1 * c1 + sum1;
        m0 = mn0;
        m1 = mn1;
        #pragma unroll
        for (int j = 0; j < 8; j++) {
            o[j][0] *= c0; o[j][1] *= c0;
            o[j][2] *= c1; o[j][3] *= c1;
        }

        #pragma unroll
        for (int kk = 0; kk < 8; kk++) {
            uint32_t ph[4], pl[4];
            split2(s[2 * kk][0],     s[2 * kk][1],     ph[0], pl[0]);
            split2(s[2 * kk][2],     s[2 * kk][3],     ph[1], pl[1]);
            split2(s[2 * kk + 1][0], s[2 * kk + 1][1], ph[2], pl[2]);
            split2(s[2 * kk + 1][2], s[2 * kk + 1][3], ph[3], pl[3]);
            #pragma unroll
            for (int j = 0; j < 8; j++) {
                int c = j * 8 + gi;
                uint32_t bh0 = Vh[(8 * kk + tg) * VP + c];
                uint32_t bh1 = Vh[(8 * kk + tg + 4) * VP + c];
                uint32_t bl0 = Vl[(8 * kk + tg) * VP + c];
                uint32_t bl1 = Vl[(8 * kk + tg + 4) * VP + c];
                mma_bf16(o[j], ph[0], ph[1], ph[2], ph[3], bh0, bh1);
                mma_bf16(o[j], pl[0], pl[1], pl[2], pl[3], bh0, bh1);
                mma_bf16(o[j], ph[0], ph[1], ph[2], ph[3], bl0, bl1);
            }
        }
    }

    // Epilogue: normalize and write PACKED bf16 hi/lo directly (fused split).
    // Thread owns cols (j*8+2tg, j*8+2tg+1) of rows r0 and r1 -> pair-word j*4+tg.
    float inv0 = 1.f / l0;
    float inv1 = 1.f / l1;
    size_t row0w = (size_t)(b * SEQT + q0 + r0) * KP2 + h * (HDIM / 2);
    size_t row1w = (size_t)(b * SEQT + q0 + r1) * KP2 + h * (HDIM / 2);
    #pragma unroll
    for (int j = 0; j < 8; j++) {
        int wi = j * 4 + tg;
        uint32_t hh, ll;
        split2(o[j][0] * inv0, o[j][1] * inv0, hh, ll);
        yh[row0w + wi] = hh;
        yl[row0w + wi] = ll;
        split2(o[j][2] * inv1, o[j][3] * inv1, hh, ll);
        yh[row1w + wi] = hh;
        yl[row1w + wi] = ll;
    }
}

// ---------------------------------------------------------------------------
extern "C" void kernel_launch(void* const* d_in, const int* in_sizes, int n_in,
                              void* d_out, int out_size)
{
    const float* x      = (const float*)d_in[0];
    const float* W_qkv  = (const float*)d_in[1];
    const float* b_qkv  = (const float*)d_in[2];
    const float* W_proj = (const float*)d_in[3];
    const float* b_proj = (const float*)d_in[4];
    float* out = (float*)d_out;

    float* qkv;
    uint32_t *xh, *xl, *yh, *yl, *wqh, *wql, *wph, *wpl;
    cudaGetSymbolAddress((void**)&qkv, g_qkv);
    cudaGetSymbolAddress((void**)&xh,  g_xh);
    cudaGetSymbolAddress((void**)&xl,  g_xl);
    cudaGetSymbolAddress((void**)&yh,  g_yh);
    cudaGetSymbolAddress((void**)&yl,  g_yl);
    cudaGetSymbolAddress((void**)&wqh, g_wqh);
    cudaGetSymbolAddress((void**)&wql, g_wql);
    cudaGetSymbolAddress((void**)&wph, g_wph);
    cudaGetSymbolAddress((void**)&wpl, g_wpl);

    cudaFuncSetAttribute(bf16x3_gemm_bias_kernel,
                         cudaFuncAttributeMaxDynamicSharedMemorySize, GEMM_SMEM);

    int n4 = MROWS * DIMV / 4;

    // Prepasses: split x; pack both weights
    split_f32_kernel<<<(n4 + 255) / 256, 256>>>((const float4*)x,
                                                (uint2*)xh, (uint2*)xl, n4);
    pack_w_kernel<<<dim3(QKV3 / 256, KP2), 256>>>(W_qkv, wqh, wql, QKV3);
    pack_w_kernel<<<dim3(DIMV / 256, KP2), 256>>>(W_proj, wph, wpl, DIMV);

    // 1) QKV projection (bf16x3, cp.async pipelined)
    bf16x3_gemm_bias_kernel<<<dim3(QKV3 / 128, MROWS / 128), 256, GEMM_SMEM>>>(
        xh, xl, wqh, wql, b_qkv, qkv, QKV3);

    // 2) Flash attention (writes packed bf16 hi/lo)
    {
        int smem_bytes = SMEM_WORDS * 4;
        cudaFuncSetAttribute(flash_attn_tc_kernel,
                             cudaFuncAttributeMaxDynamicSharedMemorySize, smem_bytes);
        dim3 grid(SEQT / BQ, NHEAD, BATCH);
        flash_attn_tc_kernel<<<grid, 256, smem_bytes>>>(qkv, yh, yl);
    }

    // 3) Output projection (reads packed attention output directly)
    bf16x3_gemm_bias_kernel<<<dim3(DIMV / 128, MROWS / 128), 256, GEMM_SMEM>>>(
        yh, yl, wph, wpl, b_proj, out, DIMV);
}

// round 14
// speedup vs baseline: 1.4519x; 1.4409x over previous
#include <cuda_runtime.h>
#include <cuda_bf16.h>
#include <cuda_fp16.h>
#include <cstdint>

#define DIMV   768
#define QKV3   2304
#define BATCH  8
#define SEQT   1024
#define NHEAD  12
#define HDIM   64
#define MROWS  (BATCH * SEQT)   // 8192
#define KP2    (DIMV / 2)       // 384 pair-words per row

// fp32 scratch
__device__ float g_qkv[(size_t)MROWS * QKV3];   // ~75.5 MB
// packed fp16 pair-words: word kp = {h(v[2kp]) low16, h(v[2kp+1]) high16}
__device__ uint32_t g_xp[(size_t)MROWS * KP2];      // x packed       [M][384]
__device__ uint32_t g_yp[(size_t)MROWS * KP2];      // attn out packed[M][384]
__device__ uint32_t g_wqp[(size_t)KP2 * QKV3];      // W_qkv packed   [384][2304]
__device__ uint32_t g_wpp[(size_t)KP2 * DIMV];      // W_proj packed  [384][768]

// ---------------------------------------------------------------------------
// Helpers
// ---------------------------------------------------------------------------
__device__ __forceinline__ uint32_t f2tf(float f) {
    uint32_t u;
    asm("cvt.rna.tf32.f32 %0, %1;" : "=r"(u) : "f"(f));
    return u;
}

__device__ __forceinline__ uint32_t smem_to_u32(const void* p) {
    uint32_t a;
    asm("{ .reg .u64 t; cvta.to.shared.u64 t, %1; cvt.u32.u64 %0, t; }"
        : "=r"(a) : "l"(p));
    return a;
}

__device__ __forceinline__ void cp_async16(uint32_t saddr, const void* gptr) {
    asm volatile("cp.async.cg.shared.global [%0], [%1], 16;"
                 :: "r"(saddr), "l"(gptr));
}
#define CP_COMMIT() asm volatile("cp.async.commit_group;" ::: "memory")
#define CP_WAIT1()  asm volatile("cp.async.wait_group 1;" ::: "memory")

__device__ __forceinline__ void mma_tf32(float* d,
                                         uint32_t a0, uint32_t a1, uint32_t a2, uint32_t a3,
                                         uint32_t b0, uint32_t b1)
{
    asm volatile(
        "mma.sync.aligned.m16n8k8.row.col.f32.tf32.tf32.f32 "
        "{%0,%1,%2,%3}, {%4,%5,%6,%7}, {%8,%9}, {%0,%1,%2,%3};\n"
        : "+f"(d[0]), "+f"(d[1]), "+f"(d[2]), "+f"(d[3])
        : "r"(a0), "r"(a1), "r"(a2), "r"(a3), "r"(b0), "r"(b1));
}

__device__ __forceinline__ void mma_bf16(float* d,
                                         uint32_t a0, uint32_t a1, uint32_t a2, uint32_t a3,
                                         uint32_t b0, uint32_t b1)
{
    asm volatile(
        "mma.sync.aligned.m16n8k16.row.col.f32.bf16.bf16.f32 "
        "{%0,%1,%2,%3}, {%4,%5,%6,%7}, {%8,%9}, {%0,%1,%2,%3};\n"
        : "+f"(d[0]), "+f"(d[1]), "+f"(d[2]), "+f"(d[3])
        : "r"(a0), "r"(a1), "r"(a2), "r"(a3), "r"(b0), "r"(b1));
}

__device__ __forceinline__ void mma_f16(float* d,
                                        uint32_t a0, uint32_t a1, uint32_t a2, uint32_t a3,
                                        uint32_t b0, uint32_t b1)
{
    asm volatile(
        "mma.sync.aligned.m16n8k16.row.col.f32.f16.f16.f32 "
        "{%0,%1,%2,%3}, {%4,%5,%6,%7}, {%8,%9}, {%0,%1,%2,%3};\n"
        : "+f"(d[0]), "+f"(d[1]), "+f"(d[2]), "+f"(d[3])
        : "r"(a0), "r"(a1), "r"(a2), "r"(a3), "r"(b0), "r"(b1));
}

__device__ __forceinline__ uint32_t pack_h2(float a, float b) {
    __half2 h = __floats2half2_rn(a, b);   // a -> low16, b -> high16
    return *reinterpret_cast<uint32_t*>(&h);
}

// bf16 hi/lo split (attention PV path, unchanged)
__device__ __forceinline__ void split2(float a, float b, uint32_t& h, uint32_t& l)
{
    __nv_bfloat16 ah = __float2bfloat16(a);
    __nv_bfloat16 bh = __float2bfloat16(b);
    h = ((uint32_t)__bfloat16_as_ushort(bh) << 16) | (uint32_t)__bfloat16_as_ushort(ah);
    __nv_bfloat16 al = __float2bfloat16(a - __bfloat162float(ah));
    __nv_bfloat16 bl = __float2bfloat16(b - __bfloat162float(bh));
    l = ((uint32_t)__bfloat16_as_ushort(bl) << 16) | (uint32_t)__bfloat16_as_ushort(al);
}

// ---------------------------------------------------------------------------
// Prepass 1: activation pack  f32[M][768] -> packed fp16 [M][384]
// ---------------------------------------------------------------------------
__global__ void pack_x_kernel(const float4* __restrict__ in,
                              uint2* __restrict__ op, int n4)
{
    int i = blockIdx.x * blockDim.x + threadIdx.x;
    if (i >= n4) return;
    float4 v = in[i];
    op[i] = make_uint2(pack_h2(v.x, v.y), pack_h2(v.z, v.w));
}

// ---------------------------------------------------------------------------
// Prepass 2: weight pack  W f32[768][Nw] -> packed fp16 [384][Nw]
// ---------------------------------------------------------------------------
__global__ void pack_w_kernel(const float* __restrict__ W,
                              uint32_t* __restrict__ op, int Nw)
{
    int n  = blockIdx.x * 256 + threadIdx.x;
    int kp = blockIdx.y;
    float a = W[(size_t)(2 * kp) * Nw + n];
    float b = W[(size_t)(2 * kp + 1) * Nw + n];
    op[(size_t)kp * Nw + n] = pack_h2(a, b);
}

// ---------------------------------------------------------------------------
// fp16 single-term GEMM, cp.async 3-stage pipeline, k=32 per stage.
// C[M,N] = A[M,768] @ B[768,N] + bias[N]
// CTA 128x128, 8 warps (4M x 2N), warp tile 32x64, mma m16n8k16 f16.
// Stage layout (words): A[128*20] | B[16*136]
// ---------------------------------------------------------------------------
#define AP     20
#define BP     136
#define A_O    0
#define B_O    2560
#define STG_W  4736
#define NSTAGE 3
#define GEMM_SMEM (NSTAGE * STG_W * 4)    // 56832 B

__global__ __launch_bounds__(256, 2)
void fp16_gemm_bias_kernel(const uint32_t* __restrict__ Ag,   // [M][384]
                           const uint32_t* __restrict__ Bg,   // [384][N]
                           const float* __restrict__ bias,
                           float* __restrict__ C,
                           int N)
{
    extern __shared__ __align__(16) uint32_t smg[];
    uint32_t sbase = smem_to_u32(smg);

    int tid  = threadIdx.x;
    int w    = tid >> 5;
    int lane = tid & 31;
    int gi   = lane >> 2;
    int tg   = lane & 3;
    int wm   = (w & 3) * 32;
    int wn   = (w >> 2) * 64;
    int m0   = blockIdx.y * 128;
    int n0   = blockIdx.x * 128;

    // staging: A rows tid>>1, 8 words each half-thread; B rows tid>>4, 8 cols blocks
    int arow = tid >> 1;             // 0..127
    int aw8  = (tid & 1) * 8;        // 0 or 8
    int bkp  = tid >> 4;             // 0..15
    int bn8  = (tid & 15) * 8;       // 0..120

    uint32_t a_soff = (uint32_t)(arow * AP + aw8) * 4;
    uint32_t b_soff = (uint32_t)(bkp * BP + bn8) * 4;
    const uint32_t* gA = Ag + (size_t)(m0 + arow) * KP2 + aw8;
    const uint32_t* gB = Bg + (size_t)bkp * N + n0 + bn8;

    const int NCH = KP2 / 16;        // 24 stages of 16 pair-words (k32)

    float acc[2][8][4];
    #pragma unroll
    for (int mi = 0; mi < 2; mi++)
        #pragma unroll
        for (int nb = 0; nb < 8; nb++)
            #pragma unroll
            for (int e = 0; e < 4; e++) acc[mi][nb][e] = 0.f;

    // Prologue: issue stages 0 and 1
    #pragma unroll
    for (int p = 0; p < 2; p++) {
        uint32_t sb = sbase + p * STG_W * 4;
        cp_async16(sb + A_O * 4 + a_soff,      gA + p * 16);
        cp_async16(sb + A_O * 4 + a_soff + 16, gA + p * 16 + 4);
        cp_async16(sb + B_O * 4 + b_soff,      gB + (size_t)p * 16 * N);
        cp_async16(sb + B_O * 4 + b_soff + 16, gB + (size_t)p * 16 * N + 4);
        CP_COMMIT();
    }

    int st = 0;
    for (int ch = 0; ch < NCH; ch++) {
        CP_WAIT1();
        __syncthreads();

        if (ch + 2 < NCH) {
            int ns = st + 2;
            if (ns >= NSTAGE) ns -= NSTAGE;
            uint32_t sb = sbase + ns * STG_W * 4;
            cp_async16(sb + A_O * 4 + a_soff,      gA + (ch + 2) * 16);
            cp_async16(sb + A_O * 4 + a_soff + 16, gA + (ch + 2) * 16 + 4);
            cp_async16(sb + B_O * 4 + b_soff,      gB + (size_t)(ch + 2) * 16 * N);
            cp_async16(sb + B_O * 4 + b_soff + 16, gB + (size_t)(ch + 2) * 16 * N + 4);
        }
        CP_COMMIT();

        const uint32_t* S = smg + st * STG_W;

        #pragma unroll
        for (int ks = 0; ks < 2; ks++) {
            int ko = ks * 8;
            uint32_t a[2][4];
            #pragma unroll
            for (int mi = 0; mi < 2; mi++) {
                int r = wm + mi * 16 + gi;
                a[mi][0] = S[A_O + r * AP + ko + tg];
                a[mi][1] = S[A_O + (r + 8) * AP + ko + tg];
                a[mi][2] = S[A_O + r * AP + ko + tg + 4];
                a[mi][3] = S[A_O + (r + 8) * AP + ko + tg + 4];
            }
            #pragma unroll
            for (int nb = 0; nb < 8; nb++) {
                int c = wn + nb * 8 + gi;
                uint32_t b0 = S[B_O + (ko + tg) * BP + c];
                uint32_t b1 = S[B_O + (ko + tg + 4) * BP + c];
                #pragma unroll
                for (int mi = 0; mi < 2; mi++)
                    mma_f16(acc[mi][nb], a[mi][0], a[mi][1], a[mi][2], a[mi][3], b0, b1);
            }
        }

        if (++st == NSTAGE) st = 0;
    }

    // Epilogue: bias + store
    #pragma unroll
    for (int mi = 0; mi < 2; mi++) {
        int r = m0 + wm + mi * 16 + gi;
        #pragma unroll
        for (int nb = 0; nb < 8; nb++) {
            int c = n0 + wn + nb * 8 + 2 * tg;
            float2 bv = *(const float2*)&bias[c];
            *(float2*)&C[(size_t)r * N + c] =
                make_float2(acc[mi][nb][0] + bv.x, acc[mi][nb][1] + bv.y);
            *(float2*)&C[(size_t)(r + 8) * N + c] =
                make_float2(acc[mi][nb][2] + bv.x, acc[mi][nb][3] + bv.y);
        }
    }
}

// ---------------------------------------------------------------------------
// Flash attention: QK tf32, softmax in regs, PV bf16 fragment-reuse 3-term.
// Epilogue writes PACKED fp16 pair-words (proj-GEMM input) directly.
// ---------------------------------------------------------------------------
#define BQ     128
#define BKV    128
#define QKP    68
#define VP     72

#define QS_OFF  0
#define KS_OFF  (QS_OFF + BQ * QKP)
#define VH_OFF  (KS_OFF + BKV * QKP)
#define VL_OFF  (VH_OFF + (BKV/2) * VP)
#define SMEM_WORDS (VL_OFF + (BKV/2) * VP)

__global__ __launch_bounds__(256, 2)
void flash_attn_tc_kernel(const float* __restrict__ qkv,
                          uint32_t* __restrict__ yp)
{
    extern __shared__ uint32_t sm[];
    uint32_t* Qs = sm + QS_OFF;
    uint32_t* Ks = sm + KS_OFF;
    uint32_t* Vh = sm + VH_OFF;
    uint32_t* Vl = sm + VL_OFF;

    int tid  = threadIdx.x;
    int w    = tid >> 5;
    int lane = tid & 31;
    int gi   = lane >> 2;
    int tg   = lane & 3;
    int q0   = blockIdx.x * BQ;
    int h    = blockIdx.y;
    int b    = blockIdx.z;
    const float SCALE = 0.125f;

    size_t base = (size_t)b * SEQT * QKV3;
    int qoff = h * HDIM;
    int koff = DIMV + h * HDIM;
    int voff = 2 * DIMV + h * HDIM;

    #pragma unroll
    for (int it = 0; it < 8; it++) {
        int idx = tid + it * 256;
        int r   = idx >> 4;
        int c4  = (idx & 15) * 4;
        float4 v = *(const float4*)&qkv[base + (size_t)(q0 + r) * QKV3 + qoff + c4];
        uint4 t;
        t.x = f2tf(v.x); t.y = f2tf(v.y); t.z = f2tf(v.z); t.w = f2tf(v.w);
        *(uint4*)&Qs[r * QKP + c4] = t;
    }

    int r0 = w * 16 + gi;
    int r1 = r0 + 8;

    float m0 = -1e30f, m1 = -1e30f;
    float l0 = 0.f, l1 = 0.f;
    float o[8][4];
    #pragma unroll
    for (int j = 0; j < 8; j++)
        #pragma unroll
        for (int e = 0; e < 4; e++) o[j][e] = 0.f;

    for (int kv0 = 0; kv0 < SEQT; kv0 += BKV) {
        __syncthreads();

        #pragma unroll
        for (int it = 0; it < 8; it++) {
            int idx = tid + it * 256;
            int r   = idx >> 4;
            int c4  = (idx & 15) * 4;
            size_t row = base + (size_t)(kv0 + r) * QKV3;
            float4 kvv = *(const float4*)&qkv[row + koff + c4];
            uint4 tk;
            tk.x = f2tf(kvv.x); tk.y = f2tf(kvv.y); tk.z = f2tf(kvv.z); tk.w = f2tf(kvv.w);
            *(uint4*)&Ks[r * QKP + c4] = tk;
        }
        #pragma unroll
        for (int it = 0; it < 4; it++) {
            int t   = tid + it * 256;
            int kp  = t >> 4;
            int c4  = (t & 15) * 4;
            size_t rowa = base + (size_t)(kv0 + 2 * kp) * QKV3 + voff + c4;
            size_t rowb = rowa + QKV3;
            float4 va = *(const float4*)&qkv[rowa];
            float4 vb = *(const float4*)&qkv[rowb];
            uint4 hh, ll;
            split2(va.x, vb.x, hh.x, ll.x);
            split2(va.y, vb.y, hh.y, ll.y);
            split2(va.z, vb.z, hh.z, ll.z);
            split2(va.w, vb.w, hh.w, ll.w);
            *(uint4*)&Vh[kp * VP + c4] = hh;
            *(uint4*)&Vl[kp * VP + c4] = ll;
        }
        __syncthreads();

        float s[16][4];
        #pragma unroll
        for (int j = 0; j < 16; j++)
            #pragma unroll
            for (int e = 0; e < 4; e++) s[j][e] = 0.f;

        #pragma unroll
        for (int kk = 0; kk < 8; kk++) {
            int d0 = kk * 8;
            uint32_t a0 = Qs[r0 * QKP + d0 + tg];
            uint32_t a1 = Qs[r1 * QKP + d0 + tg];
            uint32_t a2 = Qs[r0 * QKP + d0 + tg + 4];
            uint32_t a3 = Qs[r1 * QKP + d0 + tg + 4];
            #pragma unroll
            for (int j = 0; j < 16; j++) {
                uint32_t b0 = Ks[(j * 8 + gi) * QKP + d0 + tg];
                uint32_t b1 = Ks[(j * 8 + gi) * QKP + d0 + tg + 4];
                mma_tf32(s[j], a0, a1, a2, a3, b0, b1);
            }
        }

        float mx0 = -1e30f, mx1 = -1e30f;
        #pragma unroll
        for (int j = 0; j < 16; j++) {
            mx0 = fmaxf(mx0, fmaxf(s[j][0], s[j][1]));
            mx1 = fmaxf(mx1, fmaxf(s[j][2], s[j][3]));
        }
        #pragma unroll
        for (int msk = 1; msk < 4; msk <<= 1) {
            mx0 = fmaxf(mx0, __shfl_xor_sync(0xffffffffu, mx0, msk));
            mx1 = fmaxf(mx1, __shfl_xor_sync(0xffffffffu, mx1, msk));
        }
        float mn0 = fmaxf(m0, mx0 * SCALE);
        float mn1 = fmaxf(m1, mx1 * SCALE);
        float c0 = __expf(m0 - mn0);
        float c1 = __expf(m1 - mn1);

        float sum0 = 0.f, sum1 = 0.f;
        #pragma unroll
        for (int j = 0; j < 16; j++) {
            s[j][0] = __expf(s[j][0] * SCALE - mn0);
            s[j][1] = __expf(s[j][1] * SCALE - mn0);
            s[j][2] = __expf(s[j][2] * SCALE - mn1);
            s[j][3] = __expf(s[j][3] * SCALE - mn1);
            sum0 += s[j][0] + s[j][1];
            sum1 += s[j][2] + s[j][3];
        }
        #pragma unroll
        for (int msk = 1; msk < 4; msk <<= 1) {
            sum0 += __shfl_xor_sync(0xffffffffu, sum0, msk);
            sum1 += __shfl_xor_sync(0xffffffffu, sum1, msk);
        }
        l0 = l0 * c0 + sum0;
        l1 = l1 * c1 + sum1;
        m0 = mn0;
        m1 = mn1;
        #pragma unroll
        for (int j = 0; j < 8; j++) {
            o[j][0] *= c0; o[j][1] *= c0;
            o[j][2] *= c1; o[j][3] *= c1;
        }

        #pragma unroll
        for (int kk = 0; kk < 8; kk++) {
            uint32_t ph[4], pl[4];
            split2(s[2 * kk][0],     s[2 * kk][1],     ph[0], pl[0]);
            split2(s[2 * kk][2],     s[2 * kk][3],     ph[1], pl[1]);
            split2(s[2 * kk + 1][0], s[2 * kk + 1][1], ph[2], pl[2]);
            split2(s[2 * kk + 1][2], s[2 * kk + 1][3], ph[3], pl[3]);
            #pragma unroll
            for (int j = 0; j < 8; j++) {
                int c = j * 8 + gi;
                uint32_t bh0 = Vh[(8 * kk + tg) * VP + c];
                uint32_t bh1 = Vh[(8 * kk + tg + 4) * VP + c];
                uint32_t bl0 = Vl[(8 * kk + tg) * VP + c];
                uint32_t bl1 = Vl[(8 * kk + tg + 4) * VP + c];
                mma_bf16(o[j], ph[0], ph[1], ph[2], ph[3], bh0, bh1);
                mma_bf16(o[j], pl[0], pl[1], pl[2], pl[3], bh0, bh1);
                mma_bf16(o[j], ph[0], ph[1], ph[2], ph[3], bl0, bl1);
            }
        }
    }

    // Epilogue: normalize and write packed fp16 pair-words directly.
    // Thread owns cols (j*8+2tg, j*8+2tg+1) of rows r0,r1 -> pair-word j*4+tg.
    float inv0 = 1.f / l0;
    float inv1 = 1.f / l1;
    size_t row0w = (size_t)(b * SEQT + q0 + r0) * KP2 + h * (HDIM / 2);
    size_t row1w = (size_t)(b * SEQT + q0 + r1) * KP2 + h * (HDIM / 2);
    #pragma unroll
    for (int j = 0; j < 8; j++) {
        int wi = j * 4 + tg;
        yp[row0w + wi] = pack_h2(o[j][0] * inv0, o[j][1] * inv0);
        yp[row1w + wi] = pack_h2(o[j][2] * inv1, o[j][3] * inv1);
    }
}

// ---------------------------------------------------------------------------
extern "C" void kernel_launch(void* const* d_in, const int* in_sizes, int n_in,
                              void* d_out, int out_size)
{
    const float* x      = (const float*)d_in[0];
    const float* W_qkv  = (const float*)d_in[1];
    const float* b_qkv  = (const float*)d_in[2];
    const float* W_proj = (const float*)d_in[3];
    const float* b_proj = (const float*)d_in[4];
    float* out = (float*)d_out;

    float* qkv;
    uint32_t *xp, *yp, *wqp, *wpp;
    cudaGetSymbolAddress((void**)&qkv, g_qkv);
    cudaGetSymbolAddress((void**)&xp,  g_xp);
    cudaGetSymbolAddress((void**)&yp,  g_yp);
    cudaGetSymbolAddress((void**)&wqp, g_wqp);
    cudaGetSymbolAddress((void**)&wpp, g_wpp);

    cudaFuncSetAttribute(fp16_gemm_bias_kernel,
                         cudaFuncAttributeMaxDynamicSharedMemorySize, GEMM_SMEM);

    int n4 = MROWS * DIMV / 4;

    // Prepasses: pack x; pack both weights (fp16)
    pack_x_kernel<<<(n4 + 255) / 256, 256>>>((const float4*)x, (uint2*)xp, n4);
    pack_w_kernel<<<dim3(QKV3 / 256, KP2), 256>>>(W_qkv, wqp, QKV3);
    pack_w_kernel<<<dim3(DIMV / 256, KP2), 256>>>(W_proj, wpp, DIMV);

    // 1) QKV projection (fp16 single-term, cp.async pipelined)
    fp16_gemm_bias_kernel<<<dim3(QKV3 / 128, MROWS / 128), 256, GEMM_SMEM>>>(
        xp, wqp, b_qkv, qkv, QKV3);

    // 2) Flash attention (writes packed fp16)
    {
        int smem_bytes = SMEM_WORDS * 4;
        cudaFuncSetAttribute(flash_attn_tc_kernel,
                             cudaFuncAttributeMaxDynamicSharedMemorySize, smem_bytes);
        dim3 grid(SEQT / BQ, NHEAD, BATCH);
        flash_attn_tc_kernel<<<grid, 256, smem_bytes>>>(qkv, yp);
    }

    // 3) Output projection (fp16 single-term)
    fp16_gemm_bias_kernel<<<dim3(DIMV / 128, MROWS / 128), 256, GEMM_SMEM>>>(
        yp, wpp, b_proj, out, DIMV);
}

// round 15
// speedup vs baseline: 2.0215x; 1.3924x over previous
#include <cuda_runtime.h>
#include <cuda_bf16.h>
#include <cuda_fp16.h>
#include <cstdint>

#define DIMV   768
#define QKV3   2304
#define BATCH  8
#define SEQT   1024
#define NHEAD  12
#define HDIM   64
#define MROWS  (BATCH * SEQT)   // 8192
#define KP2    (DIMV / 2)       // 384 pair-words per row

// fp32 scratch
__device__ float g_qkv[(size_t)MROWS * QKV3];   // ~75.5 MB
// packed fp16 pair-words: word kp = {h(v[2kp]) low16, h(v[2kp+1]) high16}
__device__ uint32_t g_xp[(size_t)MROWS * KP2];      // x packed       [M][384]
__device__ uint32_t g_yp[(size_t)MROWS * KP2];      // attn out packed[M][384]
__device__ uint32_t g_wqp[(size_t)KP2 * QKV3];      // W_qkv packed   [384][2304]
__device__ uint32_t g_wpp[(size_t)KP2 * DIMV];      // W_proj packed  [384][768]

// ---------------------------------------------------------------------------
// Helpers
// ---------------------------------------------------------------------------
__device__ __forceinline__ uint32_t smem_to_u32(const void* p) {
    uint32_t a;
    asm("{ .reg .u64 t; cvta.to.shared.u64 t, %1; cvt.u32.u64 %0, t; }"
        : "=r"(a) : "l"(p));
    return a;
}

__device__ __forceinline__ void cp_async16(uint32_t saddr, const void* gptr) {
    asm volatile("cp.async.cg.shared.global [%0], [%1], 16;"
                 :: "r"(saddr), "l"(gptr));
}
#define CP_COMMIT() asm volatile("cp.async.commit_group;" ::: "memory")
#define CP_WAIT1()  asm volatile("cp.async.wait_group 1;" ::: "memory")

__device__ __forceinline__ void mma_f16(float* d,
                                        uint32_t a0, uint32_t a1, uint32_t a2, uint32_t a3,
                                        uint32_t b0, uint32_t b1)
{
    asm volatile(
        "mma.sync.aligned.m16n8k16.row.col.f32.f16.f16.f32 "
        "{%0,%1,%2,%3}, {%4,%5,%6,%7}, {%8,%9}, {%0,%1,%2,%3};\n"
        : "+f"(d[0]), "+f"(d[1]), "+f"(d[2]), "+f"(d[3])
        : "r"(a0), "r"(a1), "r"(a2), "r"(a3), "r"(b0), "r"(b1));
}

__device__ __forceinline__ uint32_t pack_h2(float a, float b) {
    __half2 h = __floats2half2_rn(a, b);   // a -> low16, b -> high16
    return *reinterpret_cast<uint32_t*>(&h);
}

// ---------------------------------------------------------------------------
// Prepass 1: activation pack  f32[M][768] -> packed fp16 [M][384]
// ---------------------------------------------------------------------------
__global__ void pack_x_kernel(const float4* __restrict__ in,
                              uint2* __restrict__ op, int n4)
{
    int i = blockIdx.x * blockDim.x + threadIdx.x;
    if (i >= n4) return;
    float4 v = in[i];
    op[i] = make_uint2(pack_h2(v.x, v.y), pack_h2(v.z, v.w));
}

// ---------------------------------------------------------------------------
// Prepass 2: weight pack  W f32[768][Nw] -> packed fp16 [384][Nw]
// ---------------------------------------------------------------------------
__global__ void pack_w_kernel(const float* __restrict__ W,
                              uint32_t* __restrict__ op, int Nw)
{
    int n  = blockIdx.x * 256 + threadIdx.x;
    int kp = blockIdx.y;
    float a = W[(size_t)(2 * kp) * Nw + n];
    float b = W[(size_t)(2 * kp + 1) * Nw + n];
    op[(size_t)kp * Nw + n] = pack_h2(a, b);
}

// ---------------------------------------------------------------------------
// fp16 single-term GEMM, cp.async 3-stage pipeline, k=32 per stage.
// (unchanged from R14)
// ---------------------------------------------------------------------------
#define AP     20
#define BP     136
#define A_O    0
#define B_O    2560
#define STG_W  4736
#define NSTAGE 3
#define GEMM_SMEM (NSTAGE * STG_W * 4)    // 56832 B

__global__ __launch_bounds__(256, 2)
void fp16_gemm_bias_kernel(const uint32_t* __restrict__ Ag,   // [M][384]
                           const uint32_t* __restrict__ Bg,   // [384][N]
                           const float* __restrict__ bias,
                           float* __restrict__ C,
                           int N)
{
    extern __shared__ __align__(16) uint32_t smg[];
    uint32_t sbase = smem_to_u32(smg);

    int tid  = threadIdx.x;
    int w    = tid >> 5;
    int lane = tid & 31;
    int gi   = lane >> 2;
    int tg   = lane & 3;
    int wm   = (w & 3) * 32;
    int wn   = (w >> 2) * 64;
    int m0   = blockIdx.y * 128;
    int n0   = blockIdx.x * 128;

    int arow = tid >> 1;
    int aw8  = (tid & 1) * 8;
    int bkp  = tid >> 4;
    int bn8  = (tid & 15) * 8;

    uint32_t a_soff = (uint32_t)(arow * AP + aw8) * 4;
    uint32_t b_soff = (uint32_t)(bkp * BP + bn8) * 4;
    const uint32_t* gA = Ag + (size_t)(m0 + arow) * KP2 + aw8;
    const uint32_t* gB = Bg + (size_t)bkp * N + n0 + bn8;

    const int NCH = KP2 / 16;        // 24 stages of 16 pair-words (k32)

    float acc[2][8][4];
    #pragma unroll
    for (int mi = 0; mi < 2; mi++)
        #pragma unroll
        for (int nb = 0; nb < 8; nb++)
            #pragma unroll
            for (int e = 0; e < 4; e++) acc[mi][nb][e] = 0.f;

    #pragma unroll
    for (int p = 0; p < 2; p++) {
        uint32_t sb = sbase + p * STG_W * 4;
        cp_async16(sb + A_O * 4 + a_soff,      gA + p * 16);
        cp_async16(sb + A_O * 4 + a_soff + 16, gA + p * 16 + 4);
        cp_async16(sb + B_O * 4 + b_soff,      gB + (size_t)p * 16 * N);
        cp_async16(sb + B_O * 4 + b_soff + 16, gB + (size_t)p * 16 * N + 4);
        CP_COMMIT();
    }

    int st = 0;
    for (int ch = 0; ch < NCH; ch++) {
        CP_WAIT1();
        __syncthreads();

        if (ch + 2 < NCH) {
            int ns = st + 2;
            if (ns >= NSTAGE) ns -= NSTAGE;
            uint32_t sb = sbase + ns * STG_W * 4;
            cp_async16(sb + A_O * 4 + a_soff,      gA + (ch + 2) * 16);
            cp_async16(sb + A_O * 4 + a_soff + 16, gA + (ch + 2) * 16 + 4);
            cp_async16(sb + B_O * 4 + b_soff,      gB + (size_t)(ch + 2) * 16 * N);
            cp_async16(sb + B_O * 4 + b_soff + 16, gB + (size_t)(ch + 2) * 16 * N + 4);
        }
        CP_COMMIT();

        const uint32_t* S = smg + st * STG_W;

        #pragma unroll
        for (int ks = 0; ks < 2; ks++) {
            int ko = ks * 8;
            uint32_t a[2][4];
            #pragma unroll
            for (int mi = 0; mi < 2; mi++) {
                int r = wm + mi * 16 + gi;
                a[mi][0] = S[A_O + r * AP + ko + tg];
                a[mi][1] = S[A_O + (r + 8) * AP + ko + tg];
                a[mi][2] = S[A_O + r * AP + ko + tg + 4];
                a[mi][3] = S[A_O + (r + 8) * AP + ko + tg + 4];
            }
            #pragma unroll
            for (int nb = 0; nb < 8; nb++) {
                int c = wn + nb * 8 + gi;
                uint32_t b0 = S[B_O + (ko + tg) * BP + c];
                uint32_t b1 = S[B_O + (ko + tg + 4) * BP + c];
                #pragma unroll
                for (int mi = 0; mi < 2; mi++)
                    mma_f16(acc[mi][nb], a[mi][0], a[mi][1], a[mi][2], a[mi][3], b0, b1);
            }
        }

        if (++st == NSTAGE) st = 0;
    }

    #pragma unroll
    for (int mi = 0; mi < 2; mi++) {
        int r = m0 + wm + mi * 16 + gi;
        #pragma unroll
        for (int nb = 0; nb < 8; nb++) {
            int c = n0 + wn + nb * 8 + 2 * tg;
            float2 bv = *(const float2*)&bias[c];
            *(float2*)&C[(size_t)r * N + c] =
                make_float2(acc[mi][nb][0] + bv.x, acc[mi][nb][1] + bv.y);
            *(float2*)&C[(size_t)(r + 8) * N + c] =
                make_float2(acc[mi][nb][2] + bv.x, acc[mi][nb][3] + bv.y);
        }
    }
}

// ---------------------------------------------------------------------------
// Flash attention, all-fp16 tensor path:
//   QK fp16 m16n8k16 (same 10-bit mantissa as tf32 -> no precision change,
//   half the mma count). PV fp16 single-term with fragment reuse.
//   Q/K/V staged as packed fp16 pair-words. Epilogue writes packed fp16.
// ---------------------------------------------------------------------------
#define BQ     128
#define BKV    128
#define QP     36    // pair-word pitch for Qs/Ks (banks 4gi+tg -> cf)
#define VP     72    // pair-row pitch for Vp    (banks 8tg+gi -> cf)

#define QS_OFF  0
#define KS_OFF  (QS_OFF + BQ * QP)            // 4608
#define VP_OFF  (KS_OFF + BKV * QP)           // 9216
#define SMEM_WORDS (VP_OFF + (BKV/2) * VP)    // 13824 words = 55296 B

__global__ __launch_bounds__(256, 2)
void flash_attn_tc_kernel(const float* __restrict__ qkv,
                          uint32_t* __restrict__ yp)
{
    extern __shared__ uint32_t sm[];
    uint32_t* Qs = sm + QS_OFF;
    uint32_t* Ks = sm + KS_OFF;
    uint32_t* Vp = sm + VP_OFF;

    int tid  = threadIdx.x;
    int w    = tid >> 5;
    int lane = tid & 31;
    int gi   = lane >> 2;
    int tg   = lane & 3;
    int q0   = blockIdx.x * BQ;
    int h    = blockIdx.y;
    int b    = blockIdx.z;
    const float SCALE = 0.125f;

    size_t base = (size_t)b * SEQT * QKV3;
    int qoff = h * HDIM;
    int koff = DIMV + h * HDIM;
    int voff = 2 * DIMV + h * HDIM;

    // Load Q tile -> packed fp16 pair-words [128][QP]
    #pragma unroll
    for (int it = 0; it < 8; it++) {
        int idx = tid + it * 256;
        int r   = idx >> 4;
        int c4  = (idx & 15) * 4;
        float4 v = *(const float4*)&qkv[base + (size_t)(q0 + r) * QKV3 + qoff + c4];
        *(uint2*)&Qs[r * QP + c4 / 2] =
            make_uint2(pack_h2(v.x, v.y), pack_h2(v.z, v.w));
    }

    int r0 = w * 16 + gi;
    int r1 = r0 + 8;

    float m0 = -1e30f, m1 = -1e30f;
    float l0 = 0.f, l1 = 0.f;
    float o[8][4];
    #pragma unroll
    for (int j = 0; j < 8; j++)
        #pragma unroll
        for (int e = 0; e < 4; e++) o[j][e] = 0.f;

    for (int kv0 = 0; kv0 < SEQT; kv0 += BKV) {
        __syncthreads();

        // K -> packed pair-words [128][QP]
        #pragma unroll
        for (int it = 0; it < 8; it++) {
            int idx = tid + it * 256;
            int r   = idx >> 4;
            int c4  = (idx & 15) * 4;
            size_t row = base + (size_t)(kv0 + r) * QKV3;
            float4 kvv = *(const float4*)&qkv[row + koff + c4];
            *(uint2*)&Ks[r * QP + c4 / 2] =
                make_uint2(pack_h2(kvv.x, kvv.y), pack_h2(kvv.z, kvv.w));
        }
        // V -> packed pair-along-k: word (kp, c) = {V[2kp][c], V[2kp+1][c]}
        #pragma unroll
        for (int it = 0; it < 4; it++) {
            int t   = tid + it * 256;       // 0..1023
            int kp  = t >> 4;               // 0..63
            int c4  = (t & 15) * 4;
            size_t rowa = base + (size_t)(kv0 + 2 * kp) * QKV3 + voff + c4;
            size_t rowb = rowa + QKV3;
            float4 va = *(const float4*)&qkv[rowa];
            float4 vb = *(const float4*)&qkv[rowb];
            uint4 pv;
            pv.x = pack_h2(va.x, vb.x);
            pv.y = pack_h2(va.y, vb.y);
            pv.z = pack_h2(va.z, vb.z);
            pv.w = pack_h2(va.w, vb.w);
            *(uint4*)&Vp[kp * VP + c4] = pv;
        }
        __syncthreads();

        // ---- QK: s = Q[16 x 64] @ K^T[64 x 128] (fp16, 4 k16 steps) ----
        float s[16][4];
        #pragma unroll
        for (int j = 0; j < 16; j++)
            #pragma unroll
            for (int e = 0; e < 4; e++) s[j][e] = 0.f;

        #pragma unroll
        for (int kk = 0; kk < 4; kk++) {
            int d0 = kk * 8;   // pair-word offset (16 halves per step)
            uint32_t a0 = Qs[r0 * QP + d0 + tg];
            uint32_t a1 = Qs[r1 * QP + d0 + tg];
            uint32_t a2 = Qs[r0 * QP + d0 + tg + 4];
            uint32_t a3 = Qs[r1 * QP + d0 + tg + 4];
            #pragma unroll
            for (int j = 0; j < 16; j++) {
                uint32_t b0 = Ks[(j * 8 + gi) * QP + d0 + tg];
                uint32_t b1 = Ks[(j * 8 + gi) * QP + d0 + tg + 4];
                mma_f16(s[j], a0, a1, a2, a3, b0, b1);
            }
        }

        // ---- online softmax in registers ----
        float mx0 = -1e30f, mx1 = -1e30f;
        #pragma unroll
        for (int j = 0; j < 16; j++) {
            mx0 = fmaxf(mx0, fmaxf(s[j][0], s[j][1]));
            mx1 = fmaxf(mx1, fmaxf(s[j][2], s[j][3]));
        }
        #pragma unroll
        for (int msk = 1; msk < 4; msk <<= 1) {
            mx0 = fmaxf(mx0, __shfl_xor_sync(0xffffffffu, mx0, msk));
            mx1 = fmaxf(mx1, __shfl_xor_sync(0xffffffffu, mx1, msk));
        }
        float mn0 = fmaxf(m0, mx0 * SCALE);
        float mn1 = fmaxf(m1, mx1 * SCALE);
        float c0 = __expf(m0 - mn0);
        float c1 = __expf(m1 - mn1);

        float sum0 = 0.f, sum1 = 0.f;
        #pragma unroll
        for (int j = 0; j < 16; j++) {
            s[j][0] = __expf(s[j][0] * SCALE - mn0);
            s[j][1] = __expf(s[j][1] * SCALE - mn0);
            s[j][2] = __expf(s[j][2] * SCALE - mn1);
            s[j][3] = __expf(s[j][3] * SCALE - mn1);
            sum0 += s[j][0] + s[j][1];
            sum1 += s[j][2] + s[j][3];
        }
        #pragma unroll
        for (int msk = 1; msk < 4; msk <<= 1) {
            sum0 += __shfl_xor_sync(0xffffffffu, sum0, msk);
            sum1 += __shfl_xor_sync(0xffffffffu, sum1, msk);
        }
        l0 = l0 * c0 + sum0;
        l1 = l1 * c1 + sum1;
        m0 = mn0;
        m1 = mn1;
        #pragma unroll
        for (int j = 0; j < 8; j++) {
            o[j][0] *= c0; o[j][1] *= c0;
            o[j][2] *= c1; o[j][3] *= c1;
        }

        // ---- PV: o += P[16 x 128] @ V[128 x 64] (fp16 fragment reuse) ----
        #pragma unroll
        for (int kk = 0; kk < 8; kk++) {
            uint32_t p0 = pack_h2(s[2 * kk][0],     s[2 * kk][1]);
            uint32_t p1 = pack_h2(s[2 * kk][2],     s[2 * kk][3]);
            uint32_t p2 = pack_h2(s[2 * kk + 1][0], s[2 * kk + 1][1]);
            uint32_t p3 = pack_h2(s[2 * kk + 1][2], s[2 * kk + 1][3]);
            #pragma unroll
            for (int j = 0; j < 8; j++) {
                int c = j * 8 + gi;
                uint32_t b0 = Vp[(8 * kk + tg) * VP + c];
                uint32_t b1 = Vp[(8 * kk + tg + 4) * VP + c];
                mma_f16(o[j], p0, p1, p2, p3, b0, b1);
            }
        }
    }

    // Epilogue: normalize and write packed fp16 pair-words directly.
    float inv0 = 1.f / l0;
    float inv1 = 1.f / l1;
    size_t row0w = (size_t)(b * SEQT + q0 + r0) * KP2 + h * (HDIM / 2);
    size_t row1w = (size_t)(b * SEQT + q0 + r1) * KP2 + h * (HDIM / 2);
    #pragma unroll
    for (int j = 0; j < 8; j++) {
        int wi = j * 4 + tg;
        yp[row0w + wi] = pack_h2(o[j][0] * inv0, o[j][1] * inv0);
        yp[row1w + wi] = pack_h2(o[j][2] * inv1, o[j][3] * inv1);
    }
}

// ---------------------------------------------------------------------------
extern "C" void kernel_launch(void* const* d_in, const int* in_sizes, int n_in,
                              void* d_out, int out_size)
{
    const float* x      = (const float*)d_in[0];
    const float* W_qkv  = (const float*)d_in[1];
    const float* b_qkv  = (const float*)d_in[2];
    const float* W_proj = (const float*)d_in[3];
    const float* b_proj = (const float*)d_in[4];
    float* out = (float*)d_out;

    float* qkv;
    uint32_t *xp, *yp, *wqp, *wpp;
    cudaGetSymbolAddress((void**)&qkv, g_qkv);
    cudaGetSymbolAddress((void**)&xp,  g_xp);
    cudaGetSymbolAddress((void**)&yp,  g_yp);
    cudaGetSymbolAddress((void**)&wqp, g_wqp);
    cudaGetSymbolAddress((void**)&wpp, g_wpp);

    cudaFuncSetAttribute(fp16_gemm_bias_kernel,
                         cudaFuncAttributeMaxDynamicSharedMemorySize, GEMM_SMEM);

    int n4 = MROWS * DIMV / 4;

    // Prepasses: pack x; pack both weights (fp16)
    pack_x_kernel<<<(n4 + 255) / 256, 256>>>((const float4*)x, (uint2*)xp, n4);
    pack_w_kernel<<<dim3(QKV3 / 256, KP2), 256>>>(W_qkv, wqp, QKV3);
    pack_w_kernel<<<dim3(DIMV / 256, KP2), 256>>>(W_proj, wpp, DIMV);

    // 1) QKV projection (fp16 single-term, cp.async pipelined)
    fp16_gemm_bias_kernel<<<dim3(QKV3 / 128, MROWS / 128), 256, GEMM_SMEM>>>(
        xp, wqp, b_qkv, qkv, QKV3);

    // 2) Flash attention (all-fp16 tensor path)
    {
        int smem_bytes = SMEM_WORDS * 4;
        cudaFuncSetAttribute(flash_attn_tc_kernel,
                             cudaFuncAttributeMaxDynamicSharedMemorySize, smem_bytes);
        dim3 grid(SEQT / BQ, NHEAD, BATCH);
        flash_attn_tc_kernel<<<grid, 256, smem_bytes>>>(qkv, yp);
    }

    // 3) Output projection (fp16 single-term)
    fp16_gemm_bias_kernel<<<dim3(DIMV / 128, MROWS / 128), 256, GEMM_SMEM>>>(
        yp, wpp, b_proj, out, DIMV);
}